// round 12
// baseline (speedup 1.0000x reference)
#include <cuda_runtime.h>
#include <cuda_bf16.h>
#include <mma.h>
#include <cstdint>

using namespace nvcuda;

#define BB 128
#define TT 256
#define DD 256
#define UU 1024
#define NN 2048
#define BT 32768   // BB*TT
#define NCTA 128   // persistent grid: 16 n-tiles x 8 k-slices
#define NTHR 512   // 16 warps
#define SAP 136    // padded row stride (elems) for 128-wide tiles
#define SXP 72     // padded row stride for 64-wide tiles

// single dynamic smem symbol for the whole TU
extern __shared__ __align__(1024) char dynsmem[];

// ---------------- device scratch (static, no runtime alloc) ----------------
__device__ float g_P[(size_t)BT * NN];                       // 256 MB  X@Wx
__device__ __nv_bfloat16 g_Xhi[(size_t)BT * DD];
__device__ __nv_bfloat16 g_Xlo[(size_t)BT * DD];
__device__ __nv_bfloat16 g_Wxhi[DD * NN];
__device__ __nv_bfloat16 g_Wxlo[DD * NN];
__device__ __nv_bfloat16 g_Whhi[UU * NN];
__device__ __nv_bfloat16 g_Whlo[UU * NN];
__device__ float g_tau[UU];
__device__ __nv_bfloat16 g_hhi[BB * UU];
__device__ __nv_bfloat16 g_hlo[BB * UU];
__device__ float g_part[8][BB][NN];                          // 8 MB partial sums
__device__ unsigned g_cnt;
__device__ unsigned g_gen;
__device__ unsigned g_fin;

// ---------------- cp.async helpers ----------------
#define CP_ASYNC16(dst, src) \
    asm volatile("cp.async.ca.shared.global [%0], [%1], 16;" :: "r"(dst), "l"(src))
#define CP_COMMIT() asm volatile("cp.async.commit_group;" ::: "memory")
#define CP_WAIT0()  asm volatile("cp.async.wait_group 0;" ::: "memory")
#define CP_WAIT1()  asm volatile("cp.async.wait_group 1;" ::: "memory")

__device__ __forceinline__ uint32_t smem_u32(const void* p) {
    uint32_t a;
    asm("{ .reg .u64 t; cvta.to.shared.u64 t, %1; cvt.u32.u64 %0, t; }" : "=r"(a) : "l"(p));
    return a;
}

// ---------------- split grid barrier ----------------
__device__ __forceinline__ void bar_arrive(unsigned target) {
    __syncthreads();
    if (threadIdx.x == 0) {
        __threadfence();
        if (atomicAdd(&g_cnt, 1u) == (unsigned)(NCTA - 1)) {
            g_cnt = 0u;
            __threadfence();
            atomicExch(&g_gen, target);
        }
    }
}
__device__ __forceinline__ void bar_wait(unsigned target) {
    if (threadIdx.x == 0) {
        while (*((volatile unsigned*)&g_gen) < target) __nanosleep(32);
        __threadfence();
    }
    __syncthreads();
}
__device__ __forceinline__ void bar_full(unsigned target) {
    bar_arrive(target);
    bar_wait(target);
}

// smem byte-offset layout
// gemm phase (double-buffered chunks): per buffer b (0/1), base = b*71680
//   X_HI +0 (18432), X_LO +18432, W_HI +36864 (17408), W_LO +54272  -> 71680
// scan phase: sm0 [128][SAP] bf16 (34816), sm1 +34816, ts +69632 (1024)
#define GB(b)    ((b) * 71680)
#define GX_HI(b) (GB(b) + 0)
#define GX_LO(b) (GB(b) + 18432)
#define GW_HI(b) (GB(b) + 36864)
#define GW_LO(b) (GB(b) + 54272)
#define SM_TOTAL 143360

// ================= fused persistent kernel =================
__global__ void __launch_bounds__(NTHR, 1) fused_kernel(
    const float* __restrict__ features,   // [B,T,D]
    const float* __restrict__ time_steps, // [B,T]
    const float* __restrict__ Wx,         // [D,2U]
    const float* __restrict__ Wh,         // [U,2U]
    const float* __restrict__ bias,       // [2U]
    const float* __restrict__ w_tau,      // [U]
    const float* __restrict__ h0,         // [B,U]
    float* __restrict__ out)              // [B,T,U]
{
    const int c = blockIdx.x;
    const int tid = threadIdx.x;
    const int warp = tid >> 5;
    const uint32_t sb = smem_u32(dynsmem);
    unsigned ep = 0;

    // ---------------- phase 0: prep (distributed) ----------------
    {
        const int gid = c * NTHR + tid;
        const int stride = NCTA * NTHR;
        for (int i = gid; i < BT * DD; i += stride) {
            float v = features[i];
            __nv_bfloat16 h = __float2bfloat16(v);
            g_Xhi[i] = h;
            g_Xlo[i] = __float2bfloat16(v - __bfloat162float(h));
        }
        for (int i = gid; i < DD * NN; i += stride) {
            float v = Wx[i];
            __nv_bfloat16 h = __float2bfloat16(v);
            g_Wxhi[i] = h;
            g_Wxlo[i] = __float2bfloat16(v - __bfloat162float(h));
        }
        for (int i = gid; i < UU * NN; i += stride) {
            float v = Wh[i];
            __nv_bfloat16 h = __float2bfloat16(v);
            g_Whhi[i] = h;
            g_Whlo[i] = __float2bfloat16(v - __bfloat162float(h));
        }
        for (int i = gid; i < UU; i += stride) {
            float w = w_tau[i];
            g_tau[i] = log1pf(expf(w));
        }
        for (int i = gid; i < BB * UU; i += stride) {
            float v = h0[i];
            __nv_bfloat16 h = __float2bfloat16(v);
            g_hhi[i] = h;
            g_hlo[i] = __float2bfloat16(v - __bfloat162float(h));
        }
    }
    bar_full(++ep);

    // ---------------- phase 1: P = X @ Wx (cp.async pipelined, 16 warps 4x4) ---
    {
        const int wm = warp >> 2;   // 0..3 (32-row band)
        const int wn = warp & 3;    // 0..3 (32-col band)

        for (int ti = c; ti < 4096; ti += NCTA) {
            const int mt = ti >> 4;
            const int nt = ti & 15;

            wmma::fragment<wmma::accumulator, 16, 16, 16, float> acc[2][2];
#pragma unroll
            for (int i = 0; i < 2; i++)
#pragma unroll
                for (int j = 0; j < 2; j++) wmma::fill_fragment(acc[i][j], 0.0f);

            auto stage = [&](int ch, int b) {
                for (int i = tid; i < 1024; i += NTHR) {
                    int row = i >> 3, q = i & 7;
                    uint32_t dh = sb + GX_HI(b) + (uint32_t)(row * SXP + q * 8) * 2;
                    uint32_t dl = sb + GX_LO(b) + (uint32_t)(row * SXP + q * 8) * 2;
                    const __nv_bfloat16* s = g_Xhi + (size_t)(mt * 128 + row) * DD + ch * 64 + q * 8;
                    const __nv_bfloat16* l = g_Xlo + (size_t)(mt * 128 + row) * DD + ch * 64 + q * 8;
                    CP_ASYNC16(dh, s);
                    CP_ASYNC16(dl, l);
                }
                for (int i = tid; i < 1024; i += NTHR) {
                    int row = i >> 4, q = i & 15;
                    uint32_t dh = sb + GW_HI(b) + (uint32_t)(row * SAP + q * 8) * 2;
                    uint32_t dl = sb + GW_LO(b) + (uint32_t)(row * SAP + q * 8) * 2;
                    const __nv_bfloat16* s = g_Wxhi + (size_t)(ch * 64 + row) * NN + nt * 128 + q * 8;
                    const __nv_bfloat16* l = g_Wxlo + (size_t)(ch * 64 + row) * NN + nt * 128 + q * 8;
                    CP_ASYNC16(dh, s);
                    CP_ASYNC16(dl, l);
                }
                CP_COMMIT();
            };

            stage(0, 0);
            for (int ch = 0; ch < 4; ch++) {
                const int b = ch & 1;
                if (ch < 3) { stage(ch + 1, (ch + 1) & 1); CP_WAIT1(); }
                else        { CP_WAIT0(); }
                __syncthreads();

                const __nv_bfloat16* sXhi = (const __nv_bfloat16*)(dynsmem + GX_HI(b));
                const __nv_bfloat16* sXlo = (const __nv_bfloat16*)(dynsmem + GX_LO(b));
                const __nv_bfloat16* sWhi = (const __nv_bfloat16*)(dynsmem + GW_HI(b));
                const __nv_bfloat16* sWlo = (const __nv_bfloat16*)(dynsmem + GW_LO(b));

                for (int kc = 0; kc < 4; kc++) {
                    wmma::fragment<wmma::matrix_a, 16, 16, 16, __nv_bfloat16, wmma::row_major> ahi[2], alo[2];
#pragma unroll
                    for (int m = 0; m < 2; m++) {
                        wmma::load_matrix_sync(ahi[m], sXhi + (wm * 32 + m * 16) * SXP + kc * 16, SXP);
                        wmma::load_matrix_sync(alo[m], sXlo + (wm * 32 + m * 16) * SXP + kc * 16, SXP);
                    }
#pragma unroll
                    for (int n = 0; n < 2; n++) {
                        wmma::fragment<wmma::matrix_b, 16, 16, 16, __nv_bfloat16, wmma::row_major> bhi, blo;
                        wmma::load_matrix_sync(bhi, sWhi + (kc * 16) * SAP + wn * 32 + n * 16, SAP);
                        wmma::load_matrix_sync(blo, sWlo + (kc * 16) * SAP + wn * 32 + n * 16, SAP);
#pragma unroll
                        for (int m = 0; m < 2; m++) {
                            wmma::mma_sync(acc[m][n], ahi[m], bhi, acc[m][n]);
                            wmma::mma_sync(acc[m][n], ahi[m], blo, acc[m][n]);
                            wmma::mma_sync(acc[m][n], alo[m], bhi, acc[m][n]);
                        }
                    }
                }
                __syncthreads();
            }
#pragma unroll
            for (int m = 0; m < 2; m++)
#pragma unroll
                for (int n = 0; n < 2; n++) {
                    float* pd = g_P + (size_t)(mt * 128 + wm * 32 + m * 16) * NN + nt * 128 + wn * 32 + n * 16;
                    wmma::store_matrix_sync(pd, acc[m][n], NN, wmma::mem_row_major);
                }
        }
    }
    bar_full(++ep);

    // ---------------- phase 2: persistent recurrence scan (16 warps) ----------
    {
        __nv_bfloat16* sm0 = (__nv_bfloat16*)dynsmem;               // [128][SAP]
        __nv_bfloat16* sm1 = (__nv_bfloat16*)(dynsmem + 34816);     // [128][SAP]
        float* s_ts = (float*)(dynsmem + 69632);                    // [TT]

        const int n = c & 15;
        const int ks = c >> 4;
        const int u0 = tid * 2;        // 512 threads x 2 = 1024 cols
        const int cs = warp & 7;       // 16-col strip (8 strips x 16 = 128)
        const int rh = warp >> 3;      // row half (0/1): rows rh*64 + m*16

        // one-time: stage Wh tile, load resident B fragments, ts row
        for (int i = tid; i < 2048; i += NTHR) {
            int row = i >> 4, q = i & 15;
            const uint4* sh = (const uint4*)(g_Whhi + (size_t)(ks * 128 + row) * NN + n * 128);
            const uint4* sl = (const uint4*)(g_Whlo + (size_t)(ks * 128 + row) * NN + n * 128);
            ((uint4*)(sm0 + row * SAP))[q] = sh[q];
            ((uint4*)(sm1 + row * SAP))[q] = sl[q];
        }
        for (int i = tid; i < TT; i += NTHR) s_ts[i] = time_steps[c * TT + i];
        __syncthreads();

        wmma::fragment<wmma::matrix_b, 16, 16, 16, __nv_bfloat16, wmma::row_major> Bhi[8], Blo[8];
#pragma unroll
        for (int kc = 0; kc < 8; kc++) {
            wmma::load_matrix_sync(Bhi[kc], sm0 + (kc * 16) * SAP + cs * 16, SAP);
            wmma::load_matrix_sync(Blo[kc], sm1 + (kc * 16) * SAP + cs * 16, SAP);
        }
        __syncthreads();   // all warps done reading before smem reuse

        // loop-invariant registers (2 cols/thread)
        const float2 bf_c = *(const float2*)&bias[u0];
        const float2 ba_c = *(const float2*)&bias[UU + u0];
        const float2 tu_c = *(const float2*)&g_tau[u0];
        float2 h_reg = *(const float2*)&h0[c * UU + u0];

        wmma::fragment<wmma::accumulator, 16, 16, 16, float> acc[4];

        for (int t = 0; t < TT; t++) {
            // stage h slice: rows = batch 0..127, cols = ks*128 + [0,128)
            for (int i = tid; i < 2048; i += NTHR) {
                int row = i >> 4, q = i & 15;
                ((uint4*)(sm0 + row * SAP))[q] =
                    __ldcg(((const uint4*)(g_hhi + (size_t)row * UU + ks * 128)) + q);
                ((uint4*)(sm1 + row * SAP))[q] =
                    __ldcg(((const uint4*)(g_hlo + (size_t)row * UU + ks * 128)) + q);
            }
            __syncthreads();

            // partial GEMM: h_slice @ Wh_tile (warp tile: 64 rows x 16 cols)
#pragma unroll
            for (int m = 0; m < 4; m++) wmma::fill_fragment(acc[m], 0.0f);
#pragma unroll
            for (int kc = 0; kc < 8; kc++) {
#pragma unroll
                for (int m = 0; m < 4; m++) {
                    wmma::fragment<wmma::matrix_a, 16, 16, 16, __nv_bfloat16, wmma::row_major> ahi, alo;
                    wmma::load_matrix_sync(ahi, sm0 + (rh * 64 + m * 16) * SAP + kc * 16, SAP);
                    wmma::load_matrix_sync(alo, sm1 + (rh * 64 + m * 16) * SAP + kc * 16, SAP);
                    wmma::mma_sync(acc[m], ahi, Bhi[kc], acc[m]);
                    wmma::mma_sync(acc[m], ahi, Blo[kc], acc[m]);
                    wmma::mma_sync(acc[m], alo, Bhi[kc], acc[m]);
                }
            }
#pragma unroll
            for (int m = 0; m < 4; m++) {
                float* pd = &g_part[ks][rh * 64 + m * 16][n * 128 + cs * 16];
                wmma::store_matrix_sync(pd, acc[m], NN, wmma::mem_row_major);
            }

            // barrier 1 with P/dt prefetch hidden in the wait
            const unsigned e1 = ++ep;
            bar_arrive(e1);
            const int r = c * TT + t;
            const float2 Pf = *(const float2*)&g_P[(size_t)r * NN + u0];
            const float2 Pa = *(const float2*)&g_P[(size_t)r * NN + UU + u0];
            const float dt = s_ts[t];
            bar_wait(e1);

            // reduce + LTC cell update; CTA c handles batch row b=c
            {
                float2 sf = make_float2(0.f, 0.f);
                float2 sa = make_float2(0.f, 0.f);
#pragma unroll
                for (int k2 = 0; k2 < 8; k2++) {
                    float2 vf = __ldcg((const float2*)&g_part[k2][c][u0]);
                    float2 va = __ldcg((const float2*)&g_part[k2][c][UU + u0]);
                    sf.x += vf.x; sf.y += vf.y;
                    sa.x += va.x; sa.y += va.y;
                }

                float hn[2];
#pragma unroll
                for (int j = 0; j < 2; j++) {
                    float pf = ((const float*)&sf)[j] + ((const float*)&Pf)[j] + ((const float*)&bf_c)[j];
                    float pa = ((const float*)&sa)[j] + ((const float*)&Pa)[j] + ((const float*)&ba_c)[j];
                    float f = __fdividef(1.f, 1.f + __expf(-pf));
                    float a = 1.f - __fdividef(2.f, __expf(2.f * pa) + 1.f);
                    float dec = __expf(-dt * (((const float*)&tu_c)[j] + f));
                    float ho = ((const float*)&h_reg)[j];
                    hn[j] = (ho - a) * dec + a;
                }
                h_reg = make_float2(hn[0], hn[1]);

                *(float2*)&out[(size_t)c * TT * UU + (size_t)t * UU + u0] = h_reg;

                __nv_bfloat16 hi[2], lo[2];
#pragma unroll
                for (int j = 0; j < 2; j++) {
                    hi[j] = __float2bfloat16(hn[j]);
                    lo[j] = __float2bfloat16(hn[j] - __bfloat162float(hi[j]));
                }
                *(uint32_t*)&g_hhi[c * UU + u0] = *(const uint32_t*)hi;
                *(uint32_t*)&g_hlo[c * UU + u0] = *(const uint32_t*)lo;
            }

            // barrier 2 (h published before next step's staging)
            const unsigned e2 = ++ep;
            bar_arrive(e2);
            bar_wait(e2);
        }
    }

    // ---------------- end-of-kernel barrier-state reset (replay-safe) ----------
    if (tid == 0) {
        __threadfence();
        if (atomicAdd(&g_fin, 1u) == (unsigned)(NCTA - 1)) {
            g_fin = 0u;
            g_cnt = 0u;
            g_gen = 0u;
            __threadfence();
        }
    }
}

// ---------------- launch ----------------
extern "C" void kernel_launch(void* const* d_in, const int* in_sizes, int n_in,
                              void* d_out, int out_size) {
    const float* features   = (const float*)d_in[0];
    const float* time_steps = (const float*)d_in[1];
    const float* Wx         = (const float*)d_in[2];
    const float* Wh         = (const float*)d_in[3];
    const float* bias       = (const float*)d_in[4];
    const float* w_tau      = (const float*)d_in[5];
    const float* h0         = (const float*)d_in[6];
    float* out = (float*)d_out;

    cudaFuncSetAttribute(fused_kernel,
                         cudaFuncAttributeMaxDynamicSharedMemorySize, SM_TOTAL);

    fused_kernel<<<NCTA, NTHR, SM_TOTAL>>>(features, time_steps, Wx, Wh,
                                           bias, w_tau, h0, out);
}

// round 14
// speedup vs baseline: 1.0457x; 1.0457x over previous
#include <cuda_runtime.h>
#include <cuda_bf16.h>
#include <mma.h>
#include <cstdint>

using namespace nvcuda;

#define BB 128
#define TT 256
#define DD 256
#define UU 1024
#define NN 2048
#define BT 32768   // BB*TT
#define NCTA 128   // persistent grid: 16 n-tiles x 8 k-slices
#define SAP 136    // padded row stride (elems) for 128-wide tiles
#define SXP 72     // padded row stride for 64-wide tiles

// single dynamic smem symbol for the whole TU
extern __shared__ __align__(1024) char dynsmem[];

// ---------------- device scratch (static, no runtime alloc) ----------------
__device__ float g_P[(size_t)BT * NN];                       // 256 MB  X@Wx
__device__ __nv_bfloat16 g_Xhi[(size_t)BT * DD];
__device__ __nv_bfloat16 g_Xlo[(size_t)BT * DD];
__device__ __nv_bfloat16 g_Wxhi[DD * NN];
__device__ __nv_bfloat16 g_Wxlo[DD * NN];
__device__ __nv_bfloat16 g_Whhi[UU * NN];
__device__ __nv_bfloat16 g_Whlo[UU * NN];
__device__ float g_tau[UU];
__device__ __nv_bfloat16 g_hhi[BB * UU];
__device__ __nv_bfloat16 g_hlo[BB * UU];
__device__ float g_part[8][BB][NN];                          // 8 MB partial sums
__device__ unsigned g_cnt;
__device__ unsigned g_gen;

// ---------------- cp.async helpers ----------------
#define CP_ASYNC16CG(dst, src) \
    asm volatile("cp.async.cg.shared.global [%0], [%1], 16;" :: "r"(dst), "l"(src))
#define CP_COMMIT() asm volatile("cp.async.commit_group;" ::: "memory")
#define CP_WAIT0()  asm volatile("cp.async.wait_group 0;" ::: "memory")
#define CP_WAIT1()  asm volatile("cp.async.wait_group 1;" ::: "memory")

__device__ __forceinline__ uint32_t smem_u32(const void* p) {
    uint32_t a;
    asm("{ .reg .u64 t; cvta.to.shared.u64 t, %1; cvt.u32.u64 %0, t; }" : "=r"(a) : "l"(p));
    return a;
}

// ---------------- merged prep kernel ----------------
__global__ void prep_kernel(const float* __restrict__ features,
                            const float* __restrict__ Wx,
                            const float* __restrict__ Wh,
                            const float* __restrict__ w_tau,
                            const float* __restrict__ h0) {
    const int gid = blockIdx.x * blockDim.x + threadIdx.x;
    const int stride = gridDim.x * blockDim.x;

    for (int i = gid; i < BT * DD; i += stride) {
        float v = features[i];
        __nv_bfloat16 h = __float2bfloat16(v);
        g_Xhi[i] = h;
        g_Xlo[i] = __float2bfloat16(v - __bfloat162float(h));
    }
    for (int i = gid; i < DD * NN; i += stride) {
        float v = Wx[i];
        __nv_bfloat16 h = __float2bfloat16(v);
        g_Wxhi[i] = h;
        g_Wxlo[i] = __float2bfloat16(v - __bfloat162float(h));
    }
    for (int i = gid; i < UU * NN; i += stride) {
        float v = Wh[i];
        __nv_bfloat16 h = __float2bfloat16(v);
        g_Whhi[i] = h;
        g_Whlo[i] = __float2bfloat16(v - __bfloat162float(h));
    }
    for (int i = gid; i < UU; i += stride) {
        float w = w_tau[i];
        g_tau[i] = log1pf(expf(w));
    }
    for (int i = gid; i < BB * UU; i += stride) {
        float v = h0[i];
        __nv_bfloat16 h = __float2bfloat16(v);
        g_hhi[i] = h;
        g_hlo[i] = __float2bfloat16(v - __bfloat162float(h));
    }
    if (gid == 0) { g_cnt = 0u; g_gen = 0u; }
}

// ---------------- precompute GEMM: P = X @ Wx (3x bf16 split, smem-staged) ----
// grid (256, 16): CTA tile 128(M) x 128(N), K=256 in 4 chunks of 64.
__global__ void __launch_bounds__(256) gemm_x_kernel() {
    __nv_bfloat16* smem = (__nv_bfloat16*)dynsmem;
    __nv_bfloat16* sXhi = smem;                       // [128][SXP]
    __nv_bfloat16* sXlo = sXhi + 128 * SXP;           // [128][SXP]
    __nv_bfloat16* sWhi = sXlo + 128 * SXP;           // [64][SAP]
    __nv_bfloat16* sWlo = sWhi + 64 * SAP;            // [64][SAP]

    const int mt = blockIdx.x;
    const int nt = blockIdx.y;
    const int tid = threadIdx.x;
    const int warp = tid >> 5;
    const int wm = warp >> 1;
    const int wn = warp & 1;

    wmma::fragment<wmma::accumulator, 16, 16, 16, float> acc[2][4];
#pragma unroll
    for (int i = 0; i < 2; i++)
#pragma unroll
        for (int j = 0; j < 4; j++) wmma::fill_fragment(acc[i][j], 0.0f);

    for (int ch = 0; ch < 4; ch++) {
        __syncthreads();
        for (int i = tid; i < 1024; i += 256) {
            int row = i >> 3, q = i & 7;
            const uint4* sh = (const uint4*)(g_Xhi + (size_t)(mt * 128 + row) * DD + ch * 64);
            const uint4* sl = (const uint4*)(g_Xlo + (size_t)(mt * 128 + row) * DD + ch * 64);
            ((uint4*)(sXhi + row * SXP))[q] = sh[q];
            ((uint4*)(sXlo + row * SXP))[q] = sl[q];
        }
        for (int i = tid; i < 1024; i += 256) {
            int row = i >> 4, q = i & 15;
            const uint4* sh = (const uint4*)(g_Wxhi + (size_t)(ch * 64 + row) * NN + nt * 128);
            const uint4* sl = (const uint4*)(g_Wxlo + (size_t)(ch * 64 + row) * NN + nt * 128);
            ((uint4*)(sWhi + row * SAP))[q] = sh[q];
            ((uint4*)(sWlo + row * SAP))[q] = sl[q];
        }
        __syncthreads();

        for (int kc = 0; kc < 4; kc++) {
            wmma::fragment<wmma::matrix_a, 16, 16, 16, __nv_bfloat16, wmma::row_major> ahi[2], alo[2];
#pragma unroll
            for (int m = 0; m < 2; m++) {
                wmma::load_matrix_sync(ahi[m], sXhi + (wm * 32 + m * 16) * SXP + kc * 16, SXP);
                wmma::load_matrix_sync(alo[m], sXlo + (wm * 32 + m * 16) * SXP + kc * 16, SXP);
            }
#pragma unroll
            for (int n = 0; n < 4; n++) {
                wmma::fragment<wmma::matrix_b, 16, 16, 16, __nv_bfloat16, wmma::row_major> bhi, blo;
                wmma::load_matrix_sync(bhi, sWhi + (kc * 16) * SAP + wn * 64 + n * 16, SAP);
                wmma::load_matrix_sync(blo, sWlo + (kc * 16) * SAP + wn * 64 + n * 16, SAP);
#pragma unroll
                for (int m = 0; m < 2; m++) {
                    wmma::mma_sync(acc[m][n], ahi[m], bhi, acc[m][n]);
                    wmma::mma_sync(acc[m][n], ahi[m], blo, acc[m][n]);
                    wmma::mma_sync(acc[m][n], alo[m], bhi, acc[m][n]);
                }
            }
        }
    }
#pragma unroll
    for (int m = 0; m < 2; m++)
#pragma unroll
        for (int n = 0; n < 4; n++) {
            float* pd = g_P + (size_t)(mt * 128 + wm * 32 + m * 16) * NN + nt * 128 + wn * 64 + n * 16;
            wmma::store_matrix_sync(pd, acc[m][n], NN, wmma::mem_row_major);
        }
}

// ---------------- split grid barrier ----------------
__device__ __forceinline__ void bar_arrive(unsigned target) {
    __syncthreads();
    if (threadIdx.x == 0) {
        __threadfence();
        if (atomicAdd(&g_cnt, 1u) == (unsigned)(NCTA - 1)) {
            g_cnt = 0u;
            __threadfence();
            atomicExch(&g_gen, target);
        }
    }
}
__device__ __forceinline__ void bar_wait(unsigned target) {
    if (threadIdx.x == 0) {
        while (*((volatile unsigned*)&g_gen) < target) __nanosleep(32);
        __threadfence();
    }
    __syncthreads();
}

// ---------------- persistent recurrence kernel ----------------
// CTA c: n-tile = c & 15 (128 output cols), k-slice = c >> 4 (128 K).
// Warp w owns 16-col strip. Resident B: 16 frags. h row c in registers.
// h staging pipelined with MMA via cp.async (4 chunks of 32 cols).
__global__ void __launch_bounds__(256, 1) rnn_persist_kernel(
    const float* __restrict__ ts,      // [B,T]
    const float* __restrict__ bias,    // [2U]
    const float* __restrict__ h0,      // [B,U]
    float* __restrict__ out)           // [B,T,U]
{
    __nv_bfloat16* sm0 = (__nv_bfloat16*)dynsmem;               // [128][SAP]
    __nv_bfloat16* sm1 = (__nv_bfloat16*)(dynsmem + 34816);     // [128][SAP]
    float* s_ts = (float*)(dynsmem + 69632);                    // [TT]
    const uint32_t sb0 = smem_u32(sm0);
    const uint32_t sb1 = smem_u32(sm1);

    const int c = blockIdx.x;
    const int n = c & 15;
    const int ks = c >> 4;
    const int tid = threadIdx.x;
    const int warp = tid >> 5;
    const int u0 = tid * 4;

    // ---- one-time: stage Wh tile, load resident B fragments, ts row ----
    for (int i = tid; i < 2048; i += 256) {
        int row = i >> 4, q = i & 15;
        const uint4* sh = (const uint4*)(g_Whhi + (size_t)(ks * 128 + row) * NN + n * 128);
        const uint4* sl = (const uint4*)(g_Whlo + (size_t)(ks * 128 + row) * NN + n * 128);
        ((uint4*)(sm0 + row * SAP))[q] = sh[q];
        ((uint4*)(sm1 + row * SAP))[q] = sl[q];
    }
    for (int i = tid; i < TT; i += 256) s_ts[i] = ts[c * TT + i];
    __syncthreads();

    wmma::fragment<wmma::matrix_b, 16, 16, 16, __nv_bfloat16, wmma::row_major> Bhi[8], Blo[8];
#pragma unroll
    for (int kc = 0; kc < 8; kc++) {
        wmma::load_matrix_sync(Bhi[kc], sm0 + (kc * 16) * SAP + warp * 16, SAP);
        wmma::load_matrix_sync(Blo[kc], sm1 + (kc * 16) * SAP + warp * 16, SAP);
    }
    __syncthreads();   // all warps done reading before smem reuse

    // loop-invariant registers
    const float4 bf_c = *(const float4*)&bias[u0];
    const float4 ba_c = *(const float4*)&bias[UU + u0];
    const float4 tu_c = *(const float4*)&g_tau[u0];
    float4 h_reg = *(const float4*)&h0[c * UU + u0];

    wmma::fragment<wmma::accumulator, 16, 16, 16, float> acc[8];

    // stage chunk cc: cols [cc*32, cc*32+32) of the h slice, hi+lo
    auto stageChunk = [&](int cc) {
        for (int i = tid; i < 512; i += 256) {
            int row = i >> 2, q = (i & 3) + cc * 4;
            uint32_t d0 = sb0 + (uint32_t)(row * SAP + q * 8) * 2;
            uint32_t d1 = sb1 + (uint32_t)(row * SAP + q * 8) * 2;
            const __nv_bfloat16* s0 = g_hhi + (size_t)row * UU + ks * 128 + q * 8;
            const __nv_bfloat16* s1 = g_hlo + (size_t)row * UU + ks * 128 + q * 8;
            CP_ASYNC16CG(d0, s0);
            CP_ASYNC16CG(d1, s1);
        }
        CP_COMMIT();
    };

    for (int t = 0; t < TT; t++) {
        // ---- pipelined: stage chunk cc+1 while MMA on chunk cc ----
#pragma unroll
        for (int m = 0; m < 8; m++) wmma::fill_fragment(acc[m], 0.0f);

        stageChunk(0);
#pragma unroll
        for (int cc = 0; cc < 4; cc++) {
            if (cc < 3) { stageChunk(cc + 1); CP_WAIT1(); }
            else        { CP_WAIT0(); }
            __syncthreads();
#pragma unroll
            for (int k2 = 0; k2 < 2; k2++) {
                const int kc = cc * 2 + k2;
#pragma unroll
                for (int m = 0; m < 8; m++) {
                    wmma::fragment<wmma::matrix_a, 16, 16, 16, __nv_bfloat16, wmma::row_major> ahi, alo;
                    wmma::load_matrix_sync(ahi, sm0 + (m * 16) * SAP + kc * 16, SAP);
                    wmma::load_matrix_sync(alo, sm1 + (m * 16) * SAP + kc * 16, SAP);
                    wmma::mma_sync(acc[m], ahi, Bhi[kc], acc[m]);
                    wmma::mma_sync(acc[m], ahi, Blo[kc], acc[m]);
                    wmma::mma_sync(acc[m], alo, Bhi[kc], acc[m]);
                }
            }
        }
#pragma unroll
        for (int m = 0; m < 8; m++) {
            float* pd = &g_part[ks][m * 16][n * 128 + warp * 16];
            wmma::store_matrix_sync(pd, acc[m], NN, wmma::mem_row_major);
        }

        // ---- barrier 1 with P/dt prefetch hidden in the wait ----
        const unsigned e1 = 2u * t + 1u;
        bar_arrive(e1);
        const int r = c * TT + t;
        const float4 Pf = *(const float4*)&g_P[(size_t)r * NN + u0];
        const float4 Pa = *(const float4*)&g_P[(size_t)r * NN + UU + u0];
        const float dt = s_ts[t];
        bar_wait(e1);

        // ---- reduce + LTC cell update; CTA c handles batch row b=c ----
        {
            float4 sf = make_float4(0.f, 0.f, 0.f, 0.f);
            float4 sa = make_float4(0.f, 0.f, 0.f, 0.f);
#pragma unroll
            for (int k2 = 0; k2 < 8; k2++) {
                float4 vf = __ldcg((const float4*)&g_part[k2][c][u0]);
                float4 va = __ldcg((const float4*)&g_part[k2][c][UU + u0]);
                sf.x += vf.x; sf.y += vf.y; sf.z += vf.z; sf.w += vf.w;
                sa.x += va.x; sa.y += va.y; sa.z += va.z; sa.w += va.w;
            }

            float hn[4];
#pragma unroll
            for (int j = 0; j < 4; j++) {
                float pf = ((const float*)&sf)[j] + ((const float*)&Pf)[j] + ((const float*)&bf_c)[j];
                float pa = ((const float*)&sa)[j] + ((const float*)&Pa)[j] + ((const float*)&ba_c)[j];
                float f = __fdividef(1.f, 1.f + __expf(-pf));
                float a = 1.f - __fdividef(2.f, __expf(2.f * pa) + 1.f);   // tanh
                float dec = __expf(-dt * (((const float*)&tu_c)[j] + f));
                float ho = ((const float*)&h_reg)[j];
                hn[j] = (ho - a) * dec + a;
            }
            h_reg = make_float4(hn[0], hn[1], hn[2], hn[3]);

            *(float4*)&out[(size_t)c * TT * UU + (size_t)t * UU + u0] = h_reg;

            __nv_bfloat16 hi[4], lo[4];
#pragma unroll
            for (int j = 0; j < 4; j++) {
                hi[j] = __float2bfloat16(hn[j]);
                lo[j] = __float2bfloat16(hn[j] - __bfloat162float(hi[j]));
            }
            *(uint2*)&g_hhi[c * UU + u0] = *(const uint2*)hi;
            *(uint2*)&g_hlo[c * UU + u0] = *(const uint2*)lo;
        }

        // ---- barrier 2 (h published before next step's staging) ----
        const unsigned e2 = 2u * t + 2u;
        bar_arrive(e2);
        bar_wait(e2);
    }
}

// ---------------- launch ----------------
extern "C" void kernel_launch(void* const* d_in, const int* in_sizes, int n_in,
                              void* d_out, int out_size) {
    const float* features   = (const float*)d_in[0];
    const float* time_steps = (const float*)d_in[1];
    const float* Wx         = (const float*)d_in[2];
    const float* Wh         = (const float*)d_in[3];
    const float* bias       = (const float*)d_in[4];
    const float* w_tau      = (const float*)d_in[5];
    const float* h0         = (const float*)d_in[6];
    float* out = (float*)d_out;

    const int smem_gemm = (2 * 128 * SXP + 2 * 64 * SAP) * 2;        // 71,680 B
    const int smem_rnn  = 2 * 128 * SAP * 2 + TT * 4;                // 70,656 B
    cudaFuncSetAttribute(gemm_x_kernel,
                         cudaFuncAttributeMaxDynamicSharedMemorySize, smem_gemm);
    cudaFuncSetAttribute(rnn_persist_kernel,
                         cudaFuncAttributeMaxDynamicSharedMemorySize, smem_rnn);

    // 1) merged prep: splits + tau + h init + barrier reset
    prep_kernel<<<2048, 256>>>(features, Wx, Wh, w_tau, h0);

    // 2) precompute P = X @ Wx
    {
        dim3 grid(BT / 128, NN / 128);
        gemm_x_kernel<<<grid, 256, smem_gemm>>>();
    }

    // 3) persistent sequential scan
    rnn_persist_kernel<<<NCTA, 256, smem_rnn>>>(time_steps, bias, h0, out);
}

// round 15
// speedup vs baseline: 1.0463x; 1.0006x over previous
#include <cuda_runtime.h>
#include <cuda_bf16.h>
#include <mma.h>
#include <cstdint>

using namespace nvcuda;

#define BB 128
#define TT 256
#define DD 256
#define UU 1024
#define NN 2048
#define BT 32768   // BB*TT
#define NCTA 128   // persistent grid: 16 n-tiles x 8 k-slices
#define NTHR 512   // 16 warps: warps 0-7 = group A (rows 0-63), 8-15 = group B (rows 64-127)
#define SAP 136    // padded row stride (elems) for 128-wide tiles
#define SXP 72     // padded row stride for 64-wide tiles

// single dynamic smem symbol for the whole TU
extern __shared__ __align__(1024) char dynsmem[];

// ---------------- device scratch (static, no runtime alloc) ----------------
__device__ float g_P[(size_t)BT * NN];                       // 256 MB  X@Wx
__device__ __nv_bfloat16 g_Xhi[(size_t)BT * DD];
__device__ __nv_bfloat16 g_Xlo[(size_t)BT * DD];
__device__ __nv_bfloat16 g_Wxhi[DD * NN];
__device__ __nv_bfloat16 g_Wxlo[DD * NN];
__device__ __nv_bfloat16 g_Whhi[UU * NN];
__device__ __nv_bfloat16 g_Whlo[UU * NN];
__device__ float g_tau[UU];
__device__ __nv_bfloat16 g_hhi[BB * UU];
__device__ __nv_bfloat16 g_hlo[BB * UU];
__device__ float g_part[8][BB][NN];                          // 8 MB partial sums
__device__ unsigned g_cnt;                                   // gemm/prep barrier
__device__ unsigned g_gen;
__device__ unsigned g_cnt2[2];                               // per-group scan barriers
__device__ unsigned g_gen2[2];

__device__ __forceinline__ uint32_t smem_u32(const void* p) {
    uint32_t a;
    asm("{ .reg .u64 t; cvta.to.shared.u64 t, %1; cvt.u32.u64 %0, t; }" : "=r"(a) : "l"(p));
    return a;
}

// named barrier for one 256-thread group (id 1 or 2)
#define BAR_GRP(id) asm volatile("bar.sync %0, 256;" :: "r"(id) : "memory")

// ---------------- merged prep kernel ----------------
__global__ void prep_kernel(const float* __restrict__ features,
                            const float* __restrict__ Wx,
                            const float* __restrict__ Wh,
                            const float* __restrict__ w_tau,
                            const float* __restrict__ h0) {
    const int gid = blockIdx.x * blockDim.x + threadIdx.x;
    const int stride = gridDim.x * blockDim.x;

    for (int i = gid; i < BT * DD; i += stride) {
        float v = features[i];
        __nv_bfloat16 h = __float2bfloat16(v);
        g_Xhi[i] = h;
        g_Xlo[i] = __float2bfloat16(v - __bfloat162float(h));
    }
    for (int i = gid; i < DD * NN; i += stride) {
        float v = Wx[i];
        __nv_bfloat16 h = __float2bfloat16(v);
        g_Wxhi[i] = h;
        g_Wxlo[i] = __float2bfloat16(v - __bfloat162float(h));
    }
    for (int i = gid; i < UU * NN; i += stride) {
        float v = Wh[i];
        __nv_bfloat16 h = __float2bfloat16(v);
        g_Whhi[i] = h;
        g_Whlo[i] = __float2bfloat16(v - __bfloat162float(h));
    }
    for (int i = gid; i < UU; i += stride) {
        float w = w_tau[i];
        g_tau[i] = log1pf(expf(w));
    }
    for (int i = gid; i < BB * UU; i += stride) {
        float v = h0[i];
        __nv_bfloat16 h = __float2bfloat16(v);
        g_hhi[i] = h;
        g_hlo[i] = __float2bfloat16(v - __bfloat162float(h));
    }
    if (gid == 0) {
        g_cnt = 0u; g_gen = 0u;
        g_cnt2[0] = 0u; g_cnt2[1] = 0u;
        g_gen2[0] = 0u; g_gen2[1] = 0u;
    }
}

// ---------------- precompute GEMM: P = X @ Wx (3x bf16 split, smem-staged) ----
__global__ void __launch_bounds__(256) gemm_x_kernel() {
    __nv_bfloat16* smem = (__nv_bfloat16*)dynsmem;
    __nv_bfloat16* sXhi = smem;                       // [128][SXP]
    __nv_bfloat16* sXlo = sXhi + 128 * SXP;           // [128][SXP]
    __nv_bfloat16* sWhi = sXlo + 128 * SXP;           // [64][SAP]
    __nv_bfloat16* sWlo = sWhi + 64 * SAP;            // [64][SAP]

    const int mt = blockIdx.x;
    const int nt = blockIdx.y;
    const int tid = threadIdx.x;
    const int warp = tid >> 5;
    const int wm = warp >> 1;
    const int wn = warp & 1;

    wmma::fragment<wmma::accumulator, 16, 16, 16, float> acc[2][4];
#pragma unroll
    for (int i = 0; i < 2; i++)
#pragma unroll
        for (int j = 0; j < 4; j++) wmma::fill_fragment(acc[i][j], 0.0f);

    for (int ch = 0; ch < 4; ch++) {
        __syncthreads();
        for (int i = tid; i < 1024; i += 256) {
            int row = i >> 3, q = i & 7;
            const uint4* sh = (const uint4*)(g_Xhi + (size_t)(mt * 128 + row) * DD + ch * 64);
            const uint4* sl = (const uint4*)(g_Xlo + (size_t)(mt * 128 + row) * DD + ch * 64);
            ((uint4*)(sXhi + row * SXP))[q] = sh[q];
            ((uint4*)(sXlo + row * SXP))[q] = sl[q];
        }
        for (int i = tid; i < 1024; i += 256) {
            int row = i >> 4, q = i & 15;
            const uint4* sh = (const uint4*)(g_Wxhi + (size_t)(ch * 64 + row) * NN + nt * 128);
            const uint4* sl = (const uint4*)(g_Wxlo + (size_t)(ch * 64 + row) * NN + nt * 128);
            ((uint4*)(sWhi + row * SAP))[q] = sh[q];
            ((uint4*)(sWlo + row * SAP))[q] = sl[q];
        }
        __syncthreads();

        for (int kc = 0; kc < 4; kc++) {
            wmma::fragment<wmma::matrix_a, 16, 16, 16, __nv_bfloat16, wmma::row_major> ahi[2], alo[2];
#pragma unroll
            for (int m = 0; m < 2; m++) {
                wmma::load_matrix_sync(ahi[m], sXhi + (wm * 32 + m * 16) * SXP + kc * 16, SXP);
                wmma::load_matrix_sync(alo[m], sXlo + (wm * 32 + m * 16) * SXP + kc * 16, SXP);
            }
#pragma unroll
            for (int n = 0; n < 4; n++) {
                wmma::fragment<wmma::matrix_b, 16, 16, 16, __nv_bfloat16, wmma::row_major> bhi, blo;
                wmma::load_matrix_sync(bhi, sWhi + (kc * 16) * SAP + wn * 64 + n * 16, SAP);
                wmma::load_matrix_sync(blo, sWlo + (kc * 16) * SAP + wn * 64 + n * 16, SAP);
#pragma unroll
                for (int m = 0; m < 2; m++) {
                    wmma::mma_sync(acc[m][n], ahi[m], bhi, acc[m][n]);
                    wmma::mma_sync(acc[m][n], ahi[m], blo, acc[m][n]);
                    wmma::mma_sync(acc[m][n], alo[m], bhi, acc[m][n]);
                }
            }
        }
    }
#pragma unroll
    for (int m = 0; m < 2; m++)
#pragma unroll
        for (int n = 0; n < 4; n++) {
            float* pd = g_P + (size_t)(mt * 128 + wm * 32 + m * 16) * NN + nt * 128 + wn * 64 + n * 16;
            wmma::store_matrix_sync(pd, acc[m][n], NN, wmma::mem_row_major);
        }
}

// ---------------- per-group grid barrier (128 CTAs each) ----------------
// Caller must have issued the group's named barrier BEFORE arrive (to ensure
// all group warps' work is done) and AFTER wait (to release the group).
__device__ __forceinline__ void grp_arrive(int g, int gtid, unsigned target) {
    if (gtid == 0) {
        __threadfence();
        if (atomicAdd(&g_cnt2[g], 1u) == (unsigned)(NCTA - 1)) {
            g_cnt2[g] = 0u;
            __threadfence();
            atomicExch(&g_gen2[g], target);
        }
    }
}
__device__ __forceinline__ void grp_wait(int g, int gtid, unsigned target) {
    if (gtid == 0) {
        while (*((volatile unsigned*)&g_gen2[g]) < target) __nanosleep(32);
        __threadfence();
    }
}

// smem byte-offset layout for the scan kernel
#define SM_WH_HI 0                      // [128][SAP] bf16 = 34816
#define SM_WH_LO 34816
#define SM_HA_HI 69632                  // [64][SAP] bf16 = 17408
#define SM_HA_LO 87040
#define SM_HB_HI 104448
#define SM_HB_LO 121856
#define SM_TS    139264                 // [256] f32
#define SM_SCAN_TOTAL 140288

// ---------------- persistent recurrence kernel (2 overlapped chains) --------
// CTA c: n-tile = c & 15, k-slice = c >> 4.
// Group g (warps g*8..g*8+7) handles batch rows [g*64, g*64+64).
// Group warp wg owns 16-col strip. CTA c's epilogue row = c, owned by group c>>6.
__global__ void __launch_bounds__(NTHR, 1) rnn_persist_kernel(
    const float* __restrict__ ts,      // [B,T]
    const float* __restrict__ bias,    // [2U]
    const float* __restrict__ h0,      // [B,U]
    float* __restrict__ out)           // [B,T,U]
{
    __nv_bfloat16* sWhi = (__nv_bfloat16*)(dynsmem + SM_WH_HI);
    __nv_bfloat16* sWlo = (__nv_bfloat16*)(dynsmem + SM_WH_LO);
    float* s_ts = (float*)(dynsmem + SM_TS);

    const int c = blockIdx.x;
    const int n = c & 15;
    const int ks = c >> 4;
    const int tid = threadIdx.x;
    const int warp = tid >> 5;
    const int grp = warp >> 3;          // 0 (A) or 1 (B)
    const int wg = warp & 7;            // warp in group
    const int gtid = tid & 255;         // thread in group
    const int barid = 1 + grp;          // named barrier id

    __nv_bfloat16* sHhi = (__nv_bfloat16*)(dynsmem + (grp ? SM_HB_HI : SM_HA_HI));
    __nv_bfloat16* sHlo = (__nv_bfloat16*)(dynsmem + (grp ? SM_HB_LO : SM_HA_LO));

    // ---- one-time: stage Wh tile (whole CTA), ts row ----
    for (int i = tid; i < 2048; i += NTHR) {
        int row = i >> 4, q = i & 15;
        const uint4* sh = (const uint4*)(g_Whhi + (size_t)(ks * 128 + row) * NN + n * 128);
        const uint4* sl = (const uint4*)(g_Whlo + (size_t)(ks * 128 + row) * NN + n * 128);
        ((uint4*)(sWhi + row * SAP))[q] = sh[q];
        ((uint4*)(sWlo + row * SAP))[q] = sl[q];
    }
    for (int i = tid; i < TT; i += NTHR) s_ts[i] = ts[c * TT + i];
    __syncthreads();

    // resident B fragments (per warp: its 16-col strip)
    wmma::fragment<wmma::matrix_b, 16, 16, 16, __nv_bfloat16, wmma::row_major> Bhi[8], Blo[8];
#pragma unroll
    for (int kc = 0; kc < 8; kc++) {
        wmma::load_matrix_sync(Bhi[kc], sWhi + (kc * 16) * SAP + wg * 16, SAP);
        wmma::load_matrix_sync(Blo[kc], sWlo + (kc * 16) * SAP + wg * 16, SAP);
    }

    // epilogue ownership: CTA c's batch row c belongs to group c>>6
    const bool owner = ((c >> 6) == grp);
    const int u0 = gtid * 4;
    float4 bf_c, ba_c, tu_c, h_reg;
    if (owner) {
        bf_c = *(const float4*)&bias[u0];
        ba_c = *(const float4*)&bias[UU + u0];
        tu_c = *(const float4*)&g_tau[u0];
        h_reg = *(const float4*)&h0[c * UU + u0];
    }

    wmma::fragment<wmma::accumulator, 16, 16, 16, float> acc[4];
    const int row0 = grp * 64;          // group's batch-row base

    for (int t = 0; t < TT; t++) {
        // ---- stage this group's h slice: 64 rows x 128 cols (hi/lo) ----
        for (int i = gtid; i < 1024; i += 256) {
            int row = i >> 4, q = i & 15;
            ((uint4*)(sHhi + row * SAP))[q] =
                __ldcg(((const uint4*)(g_hhi + (size_t)(row0 + row) * UU + ks * 128)) + q);
            ((uint4*)(sHlo + row * SAP))[q] =
                __ldcg(((const uint4*)(g_hlo + (size_t)(row0 + row) * UU + ks * 128)) + q);
        }
        BAR_GRP(barid);

        // ---- partial GEMM: h_slice(64 rows) @ Wh_tile, B resident ----
#pragma unroll
        for (int m = 0; m < 4; m++) wmma::fill_fragment(acc[m], 0.0f);
#pragma unroll
        for (int kc = 0; kc < 8; kc++) {
#pragma unroll
            for (int m = 0; m < 4; m++) {
                wmma::fragment<wmma::matrix_a, 16, 16, 16, __nv_bfloat16, wmma::row_major> ahi, alo;
                wmma::load_matrix_sync(ahi, sHhi + (m * 16) * SAP + kc * 16, SAP);
                wmma::load_matrix_sync(alo, sHlo + (m * 16) * SAP + kc * 16, SAP);
                wmma::mma_sync(acc[m], ahi, Bhi[kc], acc[m]);
                wmma::mma_sync(acc[m], ahi, Blo[kc], acc[m]);
                wmma::mma_sync(acc[m], alo, Bhi[kc], acc[m]);
            }
        }
#pragma unroll
        for (int m = 0; m < 4; m++) {
            float* pd = &g_part[ks][row0 + m * 16][n * 128 + wg * 16];
            wmma::store_matrix_sync(pd, acc[m], NN, wmma::mem_row_major);
        }

        // ---- group barrier 1 (partials ready) with P/dt prefetch ----
        const unsigned e1 = 2u * (unsigned)t + 1u;
        BAR_GRP(barid);
        grp_arrive(grp, gtid, e1);
        float4 Pf, Pa;
        float dt = 0.f;
        if (owner) {
            const int r = c * TT + t;
            Pf = *(const float4*)&g_P[(size_t)r * NN + u0];
            Pa = *(const float4*)&g_P[(size_t)r * NN + UU + u0];
            dt = s_ts[t];
        }
        grp_wait(grp, gtid, e1);
        BAR_GRP(barid);

        // ---- reduce + LTC cell update (owner group of CTA c only) ----
        if (owner) {
            float4 sf = make_float4(0.f, 0.f, 0.f, 0.f);
            float4 sa = make_float4(0.f, 0.f, 0.f, 0.f);
#pragma unroll
            for (int k2 = 0; k2 < 8; k2++) {
                float4 vf = __ldcg((const float4*)&g_part[k2][c][u0]);
                float4 va = __ldcg((const float4*)&g_part[k2][c][UU + u0]);
                sf.x += vf.x; sf.y += vf.y; sf.z += vf.z; sf.w += vf.w;
                sa.x += va.x; sa.y += va.y; sa.z += va.z; sa.w += va.w;
            }

            float hn[4];
#pragma unroll
            for (int j = 0; j < 4; j++) {
                float pf = ((const float*)&sf)[j] + ((const float*)&Pf)[j] + ((const float*)&bf_c)[j];
                float pa = ((const float*)&sa)[j] + ((const float*)&Pa)[j] + ((const float*)&ba_c)[j];
                float f = __fdividef(1.f, 1.f + __expf(-pf));
                float a = 1.f - __fdividef(2.f, __expf(2.f * pa) + 1.f);   // tanh
                float dec = __expf(-dt * (((const float*)&tu_c)[j] + f));
                float ho = ((const float*)&h_reg)[j];
                hn[j] = (ho - a) * dec + a;
            }
            h_reg = make_float4(hn[0], hn[1], hn[2], hn[3]);

            *(float4*)&out[(size_t)c * TT * UU + (size_t)t * UU + u0] = h_reg;

            __nv_bfloat16 hi[4], lo[4];
#pragma unroll
            for (int j = 0; j < 4; j++) {
                hi[j] = __float2bfloat16(hn[j]);
                lo[j] = __float2bfloat16(hn[j] - __bfloat162float(hi[j]));
            }
            *(uint2*)&g_hhi[c * UU + u0] = *(const uint2*)hi;
            *(uint2*)&g_hlo[c * UU + u0] = *(const uint2*)lo;
        }

        // ---- group barrier 2 (h published before next step's staging) ----
        const unsigned e2 = 2u * (unsigned)t + 2u;
        BAR_GRP(barid);
        grp_arrive(grp, gtid, e2);
        grp_wait(grp, gtid, e2);
        BAR_GRP(barid);
    }
}

// ---------------- launch ----------------
extern "C" void kernel_launch(void* const* d_in, const int* in_sizes, int n_in,
                              void* d_out, int out_size) {
    const float* features   = (const float*)d_in[0];
    const float* time_steps = (const float*)d_in[1];
    const float* Wx         = (const float*)d_in[2];
    const float* Wh         = (const float*)d_in[3];
    const float* bias       = (const float*)d_in[4];
    const float* w_tau      = (const float*)d_in[5];
    const float* h0         = (const float*)d_in[6];
    float* out = (float*)d_out;

    const int smem_gemm = (2 * 128 * SXP + 2 * 64 * SAP) * 2;        // 71,680 B
    cudaFuncSetAttribute(gemm_x_kernel,
                         cudaFuncAttributeMaxDynamicSharedMemorySize, smem_gemm);
    cudaFuncSetAttribute(rnn_persist_kernel,
                         cudaFuncAttributeMaxDynamicSharedMemorySize, SM_SCAN_TOTAL);

    // 1) merged prep: splits + tau + h init + barrier reset
    prep_kernel<<<2048, 256>>>(features, Wx, Wh, w_tau, h0);

    // 2) precompute P = X @ Wx
    {
        dim3 grid(BT / 128, NN / 128);
        gemm_x_kernel<<<grid, 256, smem_gemm>>>();
    }

    // 3) persistent sequential scan: two overlapped 64-row chains
    rnn_persist_kernel<<<NCTA, NTHR, SM_SCAN_TOTAL>>>(time_steps, bias, h0, out);
}